// round 4
// baseline (speedup 1.0000x reference)
#include <cuda_runtime.h>

#define RW 192
#define TW 182
#define TH 16
#define RH 26          // TH + 10
#define VSTRIDE 194    // u16 units; even, /2=97 odd -> good bank spread
#define NTHREADS 192
#define IMG_W 512
#define IMG_H 512
#define PLANES 96
#define NBLOCKS (3 * 32 * 96)
#define NPIX 25165824.0f

static constexpr float W0 = 0.00102838f;
static constexpr float W1 = 0.00759876f;
static constexpr float W2 = 0.03600077f;
static constexpr float W3 = 0.10936069f;
static constexpr float W4 = 0.21300553f;
static constexpr float W5 = 0.26601172f;
static constexpr float C1V = 0.0001f;
static constexpr float C2V = 0.0009f;

__device__ float g_accum;
__device__ unsigned int g_count;

__device__ __forceinline__ float wgt(int k) {
    switch (k) {
        case 0: case 10: return W0;
        case 1: case 9:  return W1;
        case 2: case 8:  return W2;
        case 3: case 7:  return W3;
        case 4: case 6:  return W4;
        default:         return W5;
    }
}

__device__ __forceinline__ unsigned short f2bf(float f) {
    unsigned short h;
    asm("cvt.rn.bf16.f32 %0, %1;" : "=h"(h) : "f"(f));
    return h;
}

// Vertical blur: global -> bf16 smem, transposed (scatter) accumulation.
template <bool YSAFE>
__device__ __forceinline__ void vblur(const float* __restrict__ p1,
                                      const float* __restrict__ p2,
                                      unsigned short* __restrict__ v16,
                                      int y0, int gx, bool xok, int tx) {
    float acc[5][11];
#pragma unroll
    for (int q = 0; q < 5; q++)
#pragma unroll
        for (int j = 0; j < 11; j++) acc[q][j] = 0.f;

#pragma unroll
    for (int r = 0; r < RH; r++) {
        const int gy = y0 - 5 + r;
        float a = 0.f, b = 0.f;
        if (YSAFE) {
            if (xok) {
                const int idx = gy * IMG_W + gx;
                a = __ldg(p1 + idx);
                b = __ldg(p2 + idx);
            }
        } else {
            const bool ok = xok && (gy >= 0) && (gy < IMG_H);
            if (ok) {
                const int idx = gy * IMG_W + gx;
                a = __ldg(p1 + idx);
                b = __ldg(p2 + idx);
            }
        }
        float pq[5];
        pq[0] = a; pq[1] = b; pq[2] = a * a; pq[3] = b * b; pq[4] = a * b;
#pragma unroll
        for (int k = 0; k < 11; k++) {
            const int o = r - k;
            if (o >= 0 && o < TH) {
                const int j = o % 11;          // compile-time after unroll
#pragma unroll
                for (int q = 0; q < 5; q++)
                    acc[q][j] = fmaf(pq[q], wgt(k), acc[q][j]);
            }
        }
        if (r >= 10) {
            const int o = r - 10;
            const int j = o % 11;
#pragma unroll
            for (int q = 0; q < 5; q++) {
                v16[(q * TH + o) * VSTRIDE + tx] = f2bf(acc[q][j]);
                acc[q][j] = 0.f;
            }
        }
    }
}

__global__ void __launch_bounds__(NTHREADS, 4)
ssim_main(const float* __restrict__ img1, const float* __restrict__ img2,
          float* __restrict__ out) {
    extern __shared__ unsigned short v16[];   // [5][TH][VSTRIDE] bf16
    __shared__ float red[NTHREADS / 32];

    const int tx = threadIdx.x;
    const int plane = blockIdx.z;
    const int x0 = blockIdx.x * TW;
    const int y0 = blockIdx.y * TH;

    const float* __restrict__ p1 = img1 + (size_t)plane * (IMG_W * IMG_H);
    const float* __restrict__ p2 = img2 + (size_t)plane * (IMG_W * IMG_H);

    const int gx = x0 - 5 + tx;
    const bool xok = (gx >= 0) && (gx < IMG_W);

    // ---------- Phase B: vertical blur ----------
    if (y0 >= 5 && y0 + TH + 5 <= IMG_H)
        vblur<true >(p1, p2, v16, y0, gx, xok, tx);
    else
        vblur<false>(p1, p2, v16, y0, gx, xok, tx);
    __syncthreads();

    // ---------- Phase C: horizontal blur + SSIM epilogue ----------
    const int row = tx & 15;      // 0..15
    const int seg = tx >> 4;      // 0..11
    const int cbase = seg * 16;
    const int xlim = (IMG_W - x0 < TW) ? (IMG_W - x0) : TW;

    // 32-bit view: one word = two adjacent bf16 columns
    const unsigned int* vw = (const unsigned int*)v16;

    float acc[5][11];
#pragma unroll
    for (int q = 0; q < 5; q++)
#pragma unroll
        for (int j = 0; j < 11; j++) acc[q][j] = 0.f;

    float lsum = 0.f;
#pragma unroll
    for (int t = 0; t < RH / 2; t++) {
        const bool pok = (cbase + 2 * t) < RW;
        unsigned int w[5];
#pragma unroll
        for (int q = 0; q < 5; q++)
            w[q] = pok ? vw[((q * TH + row) * VSTRIDE >> 1) + (cbase >> 1) + t] : 0u;

#pragma unroll
        for (int half = 0; half < 2; half++) {
            const int i = 2 * t + half;
            float pv[5];
#pragma unroll
            for (int q = 0; q < 5; q++)
                pv[q] = __uint_as_float(half ? (w[q] & 0xffff0000u) : (w[q] << 16));
#pragma unroll
            for (int k = 0; k < 11; k++) {
                const int xo = i - k;
                if (xo >= 0 && xo < 16) {
                    const int j = xo % 11;
#pragma unroll
                    for (int q = 0; q < 5; q++)
                        acc[q][j] = fmaf(pv[q], wgt(k), acc[q][j]);
                }
            }
            if (i >= 10) {
                const int xo = i - 10;
                const int j = xo % 11;
                const float mu1 = acc[0][j], mu2 = acc[1][j];
                const float e11 = acc[2][j], e22 = acc[3][j], e12 = acc[4][j];
#pragma unroll
                for (int q = 0; q < 5; q++) acc[q][j] = 0.f;

                const int xout = cbase + xo;
                if (xout < xlim) {
                    const float m11 = mu1 * mu1;
                    const float m22 = mu2 * mu2;
                    const float m12 = mu1 * mu2;
                    const float s1  = e11 - m11;
                    const float s2  = e22 - m22;
                    const float s12 = e12 - m12;
                    const float num = (2.f * m12 + C1V) * (2.f * s12 + C2V);
                    const float den = (m11 + m22 + C1V) * (s1 + s2 + C2V);
                    lsum += __fdividef(num, den);
                }
            }
        }
    }

    // ---------- reduction: shuffle -> smem -> one atomic per block ----------
#pragma unroll
    for (int off = 16; off > 0; off >>= 1)
        lsum += __shfl_xor_sync(0xffffffffu, lsum, off);
    if ((tx & 31) == 0) red[tx >> 5] = lsum;
    __syncthreads();

    if (tx == 0) {
        float bsum = 0.f;
#pragma unroll
        for (int w = 0; w < NTHREADS / 32; w++) bsum += red[w];
        atomicAdd(&g_accum, bsum);
        __threadfence();
        const unsigned int old = atomicAdd(&g_count, 1u);
        if (old == NBLOCKS - 1) {
            __threadfence();
            const float total = *(volatile float*)&g_accum;
            out[0] = 1.0f - total * (1.0f / NPIX);
            *(volatile float*)&g_accum = 0.f;
            *(volatile unsigned int*)&g_count = 0u;
        }
    }
}

extern "C" void kernel_launch(void* const* d_in, const int* in_sizes, int n_in,
                              void* d_out, int out_size) {
    const float* img1 = (const float*)d_in[0];
    const float* img2 = (const float*)d_in[1];

    const int smem = 5 * TH * VSTRIDE * (int)sizeof(unsigned short);  // 31,040 B
    cudaFuncSetAttribute(ssim_main, cudaFuncAttributeMaxDynamicSharedMemorySize, smem);

    dim3 grid((IMG_W + TW - 1) / TW, IMG_H / TH, PLANES);  // (3, 32, 96)
    ssim_main<<<grid, NTHREADS, smem>>>(img1, img2, (float*)d_out);
}

// round 5
// speedup vs baseline: 1.2750x; 1.2750x over previous
#include <cuda_runtime.h>

#define RW 192
#define TW 182
#define TH 16
#define RH 26          // TH + 10
#define VSTRIDE 194    // even (float2-aligned); /2 = 97 odd -> conflict-free LDS.64
#define NQ 4           // blurred quantities: a, b, a^2+b^2, a*b
#define NTHREADS 192
#define IMG_W 512
#define IMG_H 512
#define PLANES 96
#define NBLOCKS (3 * 32 * 96)
#define NPIX 25165824.0f

static constexpr float W0 = 0.00102838f;
static constexpr float W1 = 0.00759876f;
static constexpr float W2 = 0.03600077f;
static constexpr float W3 = 0.10936069f;
static constexpr float W4 = 0.21300553f;
static constexpr float W5 = 0.26601172f;
static constexpr float C1V = 0.0001f;
static constexpr float C2V = 0.0009f;

__device__ float g_accum;
__device__ unsigned int g_count;

__device__ __forceinline__ float wgt(int k) {
    switch (k) {
        case 0: case 10: return W0;
        case 1: case 9:  return W1;
        case 2: case 8:  return W2;
        case 3: case 7:  return W3;
        case 4: case 6:  return W4;
        default:         return W5;
    }
}

// Vertical blur: global -> smem, transposed (scatter) accumulation.
template <bool YSAFE>
__device__ __forceinline__ void vblur(const float* __restrict__ p1,
                                      const float* __restrict__ p2,
                                      float* __restrict__ v,
                                      int y0, int gx, bool xok, int tx) {
    float acc[NQ][11];
#pragma unroll
    for (int q = 0; q < NQ; q++)
#pragma unroll
        for (int j = 0; j < 11; j++) acc[q][j] = 0.f;

#pragma unroll
    for (int r = 0; r < RH; r++) {
        const int gy = y0 - 5 + r;
        float a = 0.f, b = 0.f;
        if (YSAFE) {
            if (xok) {
                const int idx = gy * IMG_W + gx;
                a = __ldg(p1 + idx);
                b = __ldg(p2 + idx);
            }
        } else {
            const bool ok = xok && (gy >= 0) && (gy < IMG_H);
            if (ok) {
                const int idx = gy * IMG_W + gx;
                a = __ldg(p1 + idx);
                b = __ldg(p2 + idx);
            }
        }
        float pq[NQ];
        pq[0] = a;
        pq[1] = b;
        pq[2] = fmaf(a, a, b * b);   // a^2 + b^2
        pq[3] = a * b;
#pragma unroll
        for (int k = 0; k < 11; k++) {
            const int o = r - k;
            if (o >= 0 && o < TH) {
                const int j = o % 11;          // compile-time after unroll
#pragma unroll
                for (int q = 0; q < NQ; q++)
                    acc[q][j] = fmaf(pq[q], wgt(k), acc[q][j]);
            }
        }
        if (r >= 10) {
            const int o = r - 10;
            const int j = o % 11;
#pragma unroll
            for (int q = 0; q < NQ; q++) {
                v[(q * TH + o) * VSTRIDE + tx] = acc[q][j];
                acc[q][j] = 0.f;
            }
        }
    }
}

__global__ void __launch_bounds__(NTHREADS, 4)
ssim_main(const float* __restrict__ img1, const float* __restrict__ img2,
          float* __restrict__ out) {
    extern __shared__ float v[];          // [NQ][TH][VSTRIDE]
    __shared__ float red[NTHREADS / 32];

    const int tx = threadIdx.x;
    const int plane = blockIdx.z;
    const int x0 = blockIdx.x * TW;
    const int y0 = blockIdx.y * TH;

    const float* __restrict__ p1 = img1 + (size_t)plane * (IMG_W * IMG_H);
    const float* __restrict__ p2 = img2 + (size_t)plane * (IMG_W * IMG_H);

    const int gx = x0 - 5 + tx;
    const bool xok = (gx >= 0) && (gx < IMG_W);

    // ---------- Phase B: vertical blur ----------
    if (y0 >= 5 && y0 + TH + 5 <= IMG_H)
        vblur<true >(p1, p2, v, y0, gx, xok, tx);
    else
        vblur<false>(p1, p2, v, y0, gx, xok, tx);
    __syncthreads();

    // ---------- Phase C: horizontal blur + SSIM epilogue ----------
    const int row = tx & 15;      // 0..15
    const int seg = tx >> 4;      // 0..11
    const int cbase = seg * 16;
    const int xlim = (IMG_W - x0 < TW) ? (IMG_W - x0) : TW;

    float acc[NQ][11];
#pragma unroll
    for (int q = 0; q < NQ; q++)
#pragma unroll
        for (int j = 0; j < 11; j++) acc[q][j] = 0.f;

    float lsum = 0.f;
#pragma unroll
    for (int t = 0; t < RH / 2; t++) {
        // Pair-load two consecutive raw columns (64-bit, conflict-free).
        const bool pok = (cbase + 2 * t) < RW;
        float2 pv2[NQ];
#pragma unroll
        for (int q = 0; q < NQ; q++) {
            if (pok)
                pv2[q] = *(const float2*)(v + (q * TH + row) * VSTRIDE + cbase + 2 * t);
            else
                pv2[q] = make_float2(0.f, 0.f);
        }
#pragma unroll
        for (int half = 0; half < 2; half++) {
            const int i = 2 * t + half;
            float pv[NQ];
#pragma unroll
            for (int q = 0; q < NQ; q++)
                pv[q] = half ? pv2[q].y : pv2[q].x;
#pragma unroll
            for (int k = 0; k < 11; k++) {
                const int xo = i - k;
                if (xo >= 0 && xo < 16) {
                    const int j = xo % 11;
#pragma unroll
                    for (int q = 0; q < NQ; q++)
                        acc[q][j] = fmaf(pv[q], wgt(k), acc[q][j]);
                }
            }
            if (i >= 10) {
                const int xo = i - 10;
                const int j = xo % 11;
                const float mu1 = acc[0][j], mu2 = acc[1][j];
                const float epp = acc[2][j], e12 = acc[3][j];
#pragma unroll
                for (int q = 0; q < NQ; q++) acc[q][j] = 0.f;

                const int xout = cbase + xo;
                if (xout < xlim) {
                    const float msum = fmaf(mu1, mu1, mu2 * mu2); // mu1^2+mu2^2
                    const float m12  = mu1 * mu2;
                    const float ssum = epp - msum;                // s1+s2
                    const float s12  = e12 - m12;
                    const float num = (2.f * m12 + C1V) * (2.f * s12 + C2V);
                    const float den = (msum + C1V) * (ssum + C2V);
                    lsum += __fdividef(num, den);
                }
            }
        }
    }

    // ---------- reduction: shuffle -> smem -> one atomic per block ----------
#pragma unroll
    for (int off = 16; off > 0; off >>= 1)
        lsum += __shfl_xor_sync(0xffffffffu, lsum, off);
    if ((tx & 31) == 0) red[tx >> 5] = lsum;
    __syncthreads();

    if (tx == 0) {
        float bsum = 0.f;
#pragma unroll
        for (int w = 0; w < NTHREADS / 32; w++) bsum += red[w];
        atomicAdd(&g_accum, bsum);
        __threadfence();
        const unsigned int old = atomicAdd(&g_count, 1u);
        if (old == NBLOCKS - 1) {
            __threadfence();
            const float total = *(volatile float*)&g_accum;
            out[0] = 1.0f - total * (1.0f / NPIX);
            *(volatile float*)&g_accum = 0.f;
            *(volatile unsigned int*)&g_count = 0u;
        }
    }
}

extern "C" void kernel_launch(void* const* d_in, const int* in_sizes, int n_in,
                              void* d_out, int out_size) {
    const float* img1 = (const float*)d_in[0];
    const float* img2 = (const float*)d_in[1];

    const int smem = NQ * TH * VSTRIDE * (int)sizeof(float);  // 49,664 B
    cudaFuncSetAttribute(ssim_main, cudaFuncAttributeMaxDynamicSharedMemorySize, smem);

    dim3 grid((IMG_W + TW - 1) / TW, IMG_H / TH, PLANES);     // (3, 32, 96)
    ssim_main<<<grid, NTHREADS, smem>>>(img1, img2, (float*)d_out);
}

// round 6
// speedup vs baseline: 1.3568x; 1.0641x over previous
#include <cuda_runtime.h>

#define RW 192
#define TW 182
#define TH 16
#define RH 26          // TH + 10
#define NQ 4           // blurred quantities: a, b, a^2+b^2, a*b
#define PITCH 772      // floats per row: 192*4 + 4 pad; 772 % 32 == 4 -> LDS.128 conflict-free
#define SMEM_FLOATS (TH * PITCH + 64)   // +64 pad: phase-C tail overreads stay in-bounds
#define NTHREADS 192
#define IMG_W 512
#define IMG_H 512
#define PLANES 96
#define NBLOCKS (3 * 32 * 96)
#define NPIX 25165824.0f

static constexpr float W0 = 0.00102838f;
static constexpr float W1 = 0.00759876f;
static constexpr float W2 = 0.03600077f;
static constexpr float W3 = 0.10936069f;
static constexpr float W4 = 0.21300553f;
static constexpr float W5 = 0.26601172f;
static constexpr float C1V = 0.0001f;
static constexpr float C2V = 0.0009f;

__device__ float g_accum;
__device__ unsigned int g_count;

__device__ __forceinline__ float wgt(int k) {
    switch (k) {
        case 0: case 10: return W0;
        case 1: case 9:  return W1;
        case 2: case 8:  return W2;
        case 3: case 7:  return W3;
        case 4: case 6:  return W4;
        default:         return W5;
    }
}

// Vertical blur: global -> interleaved smem [row][col][q].
// Fresh-output trick: tap k==0 (o==r) writes acc = pq*W0 (no zero-init needed).
template <bool YSAFE>
__device__ __forceinline__ void vblur(const float* __restrict__ p1,
                                      const float* __restrict__ p2,
                                      float* __restrict__ v,
                                      int y0, int gx, bool xok, int tx) {
    float acc[NQ][11];

#pragma unroll
    for (int r = 0; r < RH; r++) {
        const int gy = y0 - 5 + r;
        float a = 0.f, b = 0.f;
        if (YSAFE) {
            if (xok) {
                const int idx = gy * IMG_W + gx;
                a = __ldg(p1 + idx);
                b = __ldg(p2 + idx);
            }
        } else {
            const bool ok = xok && (gy >= 0) && (gy < IMG_H);
            if (ok) {
                const int idx = gy * IMG_W + gx;
                a = __ldg(p1 + idx);
                b = __ldg(p2 + idx);
            }
        }
        float pq[NQ];
        pq[0] = a;
        pq[1] = b;
        pq[2] = fmaf(a, a, b * b);   // a^2 + b^2
        pq[3] = a * b;
#pragma unroll
        for (int k = 0; k < 11; k++) {
            const int o = r - k;
            if (o >= 0 && o < TH) {
                const int j = o % 11;          // compile-time after unroll
                if (k == 0) {
#pragma unroll
                    for (int q = 0; q < NQ; q++)
                        acc[q][j] = pq[q] * W0;           // fresh output
                } else {
#pragma unroll
                    for (int q = 0; q < NQ; q++)
                        acc[q][j] = fmaf(pq[q], wgt(k), acc[q][j]);
                }
            }
        }
        if (r >= 10) {
            const int o = r - 10;
            const int j = o % 11;
            float* dst = v + o * PITCH + tx * NQ;
#pragma unroll
            for (int q = 0; q < NQ; q++)
                dst[q] = acc[q][j];
            // no zeroing: slot j is freshly MUL-written at iteration r+1
        }
    }
}

__global__ void __launch_bounds__(NTHREADS, 4)
ssim_main(const float* __restrict__ img1, const float* __restrict__ img2,
          float* __restrict__ out) {
    extern __shared__ float v[];          // [TH][PITCH] interleaved, + pad
    __shared__ float red[NTHREADS / 32];

    const int tx = threadIdx.x;
    const int plane = blockIdx.z;
    const int x0 = blockIdx.x * TW;
    const int y0 = blockIdx.y * TH;

    const float* __restrict__ p1 = img1 + (size_t)plane * (IMG_W * IMG_H);
    const float* __restrict__ p2 = img2 + (size_t)plane * (IMG_W * IMG_H);

    const int gx = x0 - 5 + tx;
    const bool xok = (gx >= 0) && (gx < IMG_W);

    // ---------- Phase B: vertical blur ----------
    if (y0 >= 5 && y0 + TH + 5 <= IMG_H)
        vblur<true >(p1, p2, v, y0, gx, xok, tx);
    else
        vblur<false>(p1, p2, v, y0, gx, xok, tx);
    __syncthreads();

    // ---------- Phase C: horizontal blur + SSIM epilogue ----------
    const int row = tx & 15;      // 0..15
    const int seg = tx >> 4;      // 0..11
    const int cbase = seg * 16;
    const int xlim = (IMG_W - x0 < TW) ? (IMG_W - x0) : TW;

    // base pointer for this thread's row; columns advance by NQ floats (16B)
    const float4* __restrict__ vrow =
        (const float4*)(v + row * PITCH) + cbase;

    float acc[NQ][11];
    float lsum = 0.f;

#pragma unroll
    for (int i = 0; i < RH; i++) {
        // One LDS.128 delivers all 4 quantities of column cbase+i.
        // For seg 11, i>15 overreads into padding: feeds only discarded outputs.
        const float4 pw = vrow[i];
        float pv[NQ] = {pw.x, pw.y, pw.z, pw.w};

#pragma unroll
        for (int k = 0; k < 11; k++) {
            const int xo = i - k;
            if (xo >= 0 && xo < 16) {
                const int j = xo % 11;
                if (k == 0) {
#pragma unroll
                    for (int q = 0; q < NQ; q++)
                        acc[q][j] = pv[q] * W0;           // fresh output
                } else {
#pragma unroll
                    for (int q = 0; q < NQ; q++)
                        acc[q][j] = fmaf(pv[q], wgt(k), acc[q][j]);
                }
            }
        }
        if (i >= 10) {
            const int xo = i - 10;
            const int j = xo % 11;
            const float mu1 = acc[0][j], mu2 = acc[1][j];
            const float epp = acc[2][j], e12 = acc[3][j];

            const int xout = cbase + xo;
            if (xout < xlim) {
                const float msum = fmaf(mu1, mu1, mu2 * mu2); // mu1^2+mu2^2
                const float m12  = mu1 * mu2;
                const float ssum = epp - msum;                // s1+s2
                const float s12  = e12 - m12;
                const float num = fmaf(2.f, m12, C1V) * fmaf(2.f, s12, C2V);
                const float den = (msum + C1V) * (ssum + C2V);
                lsum += __fdividef(num, den);
            }
        }
    }

    // ---------- reduction: shuffle -> smem -> one atomic per block ----------
#pragma unroll
    for (int off = 16; off > 0; off >>= 1)
        lsum += __shfl_xor_sync(0xffffffffu, lsum, off);
    if ((tx & 31) == 0) red[tx >> 5] = lsum;
    __syncthreads();

    if (tx == 0) {
        float bsum = 0.f;
#pragma unroll
        for (int w = 0; w < NTHREADS / 32; w++) bsum += red[w];
        atomicAdd(&g_accum, bsum);
        __threadfence();
        const unsigned int old = atomicAdd(&g_count, 1u);
        if (old == NBLOCKS - 1) {
            __threadfence();
            const float total = *(volatile float*)&g_accum;
            out[0] = 1.0f - total * (1.0f / NPIX);
            *(volatile float*)&g_accum = 0.f;
            *(volatile unsigned int*)&g_count = 0u;
        }
    }
}

extern "C" void kernel_launch(void* const* d_in, const int* in_sizes, int n_in,
                              void* d_out, int out_size) {
    const float* img1 = (const float*)d_in[0];
    const float* img2 = (const float*)d_in[1];

    const int smem = SMEM_FLOATS * (int)sizeof(float);   // 49,664 B
    cudaFuncSetAttribute(ssim_main, cudaFuncAttributeMaxDynamicSharedMemorySize, smem);

    dim3 grid((IMG_W + TW - 1) / TW, IMG_H / TH, PLANES);  // (3, 32, 96)
    ssim_main<<<grid, NTHREADS, smem>>>(img1, img2, (float*)d_out);
}

// round 8
// speedup vs baseline: 1.5089x; 1.1122x over previous
#include <cuda_runtime.h>
#include <cuda_fp16.h>

#define RW 192
#define TW 182
#define TH 16          // output rows per tile
#define NP 8           // row pairs per tile
#define RH 26          // TH + 10 input rows
#define PITCH 772      // u32 words per pair-row: 192*4 + 4; 772%32==4 -> conflict-free
#define SMEM_WORDS (NP * PITCH + 160)   // pad covers phase-C tail overreads
#define NTHREADS 192
#define IMG_W 512
#define IMG_H 512
#define PLANES 96
#define NBLOCKS (3 * 32 * 96)
#define NPIX 25165824.0f

static constexpr float C1V = 0.0001f;
static constexpr float C2V = 0.0009f;

// Gaussian(sigma=1.5, k=11) weights as a constexpr function (usable in device code)
__host__ __device__ constexpr float wt(int k) {
    return (k == 0 || k == 10) ? 0.00102838f
         : (k == 1 || k == 9)  ? 0.00759876f
         : (k == 2 || k == 8)  ? 0.03600077f
         : (k == 3 || k == 7)  ? 0.10936069f
         : (k == 4 || k == 6)  ? 0.21300553f
         : (k == 5)            ? 0.26601172f
         : 0.0f;
}

__device__ float g_accum;
__device__ unsigned int g_count;

// ---- raw half2 helpers on u32 ----
__device__ __forceinline__ unsigned hfma2u(unsigned a, unsigned b, unsigned c) {
    unsigned d; asm("fma.rn.f16x2 %0,%1,%2,%3;" : "=r"(d) : "r"(a), "r"(b), "r"(c)); return d;
}
__device__ __forceinline__ unsigned hmul2u(unsigned a, unsigned b) {
    unsigned d; asm("mul.rn.f16x2 %0,%1,%2;" : "=r"(d) : "r"(a), "r"(b)); return d;
}
__device__ __forceinline__ unsigned pack_h2(float lo, float hi) {
    unsigned d;
    asm("{\n\t.reg .b16 l, h;\n\t"
        "cvt.rn.f16.f32 l, %1;\n\t"
        "cvt.rn.f16.f32 h, %2;\n\t"
        "mov.b32 %0, {l, h};\n\t}"
        : "=r"(d) : "f"(lo), "f"(hi));
    return d;
}
__device__ __forceinline__ unsigned bcast_h2(float f) {
    unsigned d; asm("cvt.rn.f16x2.f32 %0, %1, %1;" : "=r"(d) : "f"(f)); return d;
}
__device__ __forceinline__ float2 unpack_h2(unsigned u) {
    __half2 h = *reinterpret_cast<__half2*>(&u);
    return make_float2(__low2float(h), __high2float(h));
}

// Vertical blur: global -> half2-packed smem [pair-row][col][4q].
// Lanes of each half2 = output rows (2p, 2p+1). Weight pair (w[k], w[k-1]).
template <bool YSAFE>
__device__ __forceinline__ void vblur(const float* __restrict__ p1,
                                      const float* __restrict__ p2,
                                      unsigned* __restrict__ vw,
                                      int y0, int gx, bool xok, int tx,
                                      const unsigned (&WK)[12]) {
    unsigned acc[6][4];   // ring of 6 live pairs x 4 quantities

#pragma unroll
    for (int r = 0; r < RH; r++) {
        const int gy = y0 - 5 + r;
        float a = 0.f, b = 0.f;
        if (YSAFE) {
            if (xok) {
                const int idx = gy * IMG_W + gx;
                a = __ldg(p1 + idx);
                b = __ldg(p2 + idx);
            }
        } else {
            const bool ok = xok && (gy >= 0) && (gy < IMG_H);
            if (ok) {
                const int idx = gy * IMG_W + gx;
                a = __ldg(p1 + idx);
                b = __ldg(p2 + idx);
            }
        }
        const float s = fmaf(a, a, b * b);
        const float m = a * b;
        unsigned pq[4];
        pq[0] = bcast_h2(a);
        pq[1] = bcast_h2(b);
        pq[2] = bcast_h2(s);
        pq[3] = bcast_h2(m);

#pragma unroll
        for (int p = 0; p < NP; p++) {
            const int k = r - 2 * p;            // compile-time after unroll
            if (k >= 0 && k <= 11) {
                const int j = p % 6;
                if (k == 0) {
#pragma unroll
                    for (int q = 0; q < 4; q++)
                        acc[j][q] = hmul2u(pq[q], WK[0]);   // fresh pair (lane1 *0)
                } else {
#pragma unroll
                    for (int q = 0; q < 4; q++)
                        acc[j][q] = hfma2u(pq[q], WK[k], acc[j][q]);
                }
            }
        }
        if (r >= 11 && ((r - 11) & 1) == 0) {
            const int p = (r - 11) >> 1;
            const int j = p % 6;
            uint4 w4 = make_uint4(acc[j][0], acc[j][1], acc[j][2], acc[j][3]);
            *reinterpret_cast<uint4*>(vw + p * PITCH + tx * 4) = w4;
        }
    }
}

__global__ void __launch_bounds__(NTHREADS, 4)
ssim_main(const float* __restrict__ img1, const float* __restrict__ img2,
          float* __restrict__ out) {
    extern __shared__ unsigned vw[];      // [NP][PITCH] + pad
    __shared__ float red[NTHREADS / 32];

    const int tx = threadIdx.x;
    const int plane = blockIdx.z;
    const int x0 = blockIdx.x * TW;
    const int y0 = blockIdx.y * TH;

    const float* __restrict__ p1 = img1 + (size_t)plane * (IMG_W * IMG_H);
    const float* __restrict__ p2 = img2 + (size_t)plane * (IMG_W * IMG_H);

    const int gx = x0 - 5 + tx;
    const bool xok = (gx >= 0) && (gx < IMG_W);

    // weight pairs (w[k], w[k-1]) for vertical pass; wt() is 0 out of range
    unsigned WK[12];
#pragma unroll
    for (int k = 0; k < 12; k++)
        WK[k] = pack_h2(wt(k), wt(k - 1));

    // ---------- Phase B ----------
    if (y0 >= 5 && y0 + TH + 5 <= IMG_H)
        vblur<true >(p1, p2, vw, y0, gx, xok, tx, WK);
    else
        vblur<false>(p1, p2, vw, y0, gx, xok, tx, WK);
    __syncthreads();

    // ---------- Phase C: horizontal blur + SSIM epilogue ----------
    const int rp  = tx & 7;       // pair-row 0..7 (output rows 2rp, 2rp+1)
    const int seg = tx >> 3;      // 0..23, each covers 8 output columns
    const int c0  = seg * 8;
    const int xlim = (IMG_W - x0 < TW) ? (IMG_W - x0) : TW;

    unsigned WB[6];               // broadcast weights (symmetric)
#pragma unroll
    for (int k = 0; k < 6; k++) WB[k] = bcast_h2(wt(k));

    unsigned acc[8][4];
    const unsigned* rowp = vw + rp * PITCH + c0 * 4;

#pragma unroll
    for (int i = 0; i < 18; i++) {
        // One LDS.128: 4 quantities x 2 rows of column c0+i. Tail overreads
        // (seg>=22, i large) stay in the padded allocation and feed only
        // outputs discarded by xlim.
        const uint4 w4 = *reinterpret_cast<const uint4*>(rowp + i * 4);
        unsigned pv[4] = {w4.x, w4.y, w4.z, w4.w};
#pragma unroll
        for (int xo = 0; xo < 8; xo++) {
            const int k = i - xo;
            if (k >= 0 && k <= 10) {
                const int wi = (k < 6) ? k : (10 - k);
                if (k == 0) {
#pragma unroll
                    for (int q = 0; q < 4; q++)
                        acc[xo][q] = hmul2u(pv[q], WB[0]);
                } else {
#pragma unroll
                    for (int q = 0; q < 4; q++)
                        acc[xo][q] = hfma2u(pv[q], WB[wi], acc[xo][q]);
                }
            }
        }
    }

    float lsum = 0.f;
#pragma unroll
    for (int xo = 0; xo < 8; xo++) {
        const int xout = c0 + xo;
        if (xout < xlim) {
            const float2 mu1 = unpack_h2(acc[xo][0]);
            const float2 mu2 = unpack_h2(acc[xo][1]);
            const float2 epp = unpack_h2(acc[xo][2]);
            const float2 e12 = unpack_h2(acc[xo][3]);
#pragma unroll
            for (int h = 0; h < 2; h++) {
                const float m1 = h ? mu1.y : mu1.x;
                const float m2 = h ? mu2.y : mu2.x;
                const float ep = h ? epp.y : epp.x;
                const float ex = h ? e12.y : e12.x;
                const float msum = fmaf(m1, m1, m2 * m2);
                const float m12  = m1 * m2;
                const float ssum = ep - msum;
                const float s12  = ex - m12;
                const float num = fmaf(2.f, m12, C1V) * fmaf(2.f, s12, C2V);
                const float den = (msum + C1V) * (ssum + C2V);
                lsum += __fdividef(num, den);
            }
        }
    }

    // ---------- reduction: shuffle -> smem -> one atomic per block ----------
#pragma unroll
    for (int off = 16; off > 0; off >>= 1)
        lsum += __shfl_xor_sync(0xffffffffu, lsum, off);
    if ((tx & 31) == 0) red[tx >> 5] = lsum;
    __syncthreads();

    if (tx == 0) {
        float bsum = 0.f;
#pragma unroll
        for (int w = 0; w < NTHREADS / 32; w++) bsum += red[w];
        atomicAdd(&g_accum, bsum);
        __threadfence();
        const unsigned int old = atomicAdd(&g_count, 1u);
        if (old == NBLOCKS - 1) {
            __threadfence();
            const float total = *(volatile float*)&g_accum;
            out[0] = 1.0f - total * (1.0f / NPIX);
            *(volatile float*)&g_accum = 0.f;
            *(volatile unsigned int*)&g_count = 0u;
        }
    }
}

extern "C" void kernel_launch(void* const* d_in, const int* in_sizes, int n_in,
                              void* d_out, int out_size) {
    const float* img1 = (const float*)d_in[0];
    const float* img2 = (const float*)d_in[1];

    const int smem = SMEM_WORDS * (int)sizeof(unsigned);   // 25,344 B
    cudaFuncSetAttribute(ssim_main, cudaFuncAttributeMaxDynamicSharedMemorySize, smem);

    dim3 grid((IMG_W + TW - 1) / TW, IMG_H / TH, PLANES);  // (3, 32, 96)
    ssim_main<<<grid, NTHREADS, smem>>>(img1, img2, (float*)d_out);
}